// round 9
// baseline (speedup 1.0000x reference)
#include <cuda_runtime.h>

// SSIM loss, fused separable 11x11 gaussian blur + ssim map + mean reduce.
// R9: profile showed L1TEX=90.4% -> crossbar-traffic bound. R8's interleave
// had 2-way bank conflicts (stride 6 -> gcd(6,32)=2) -> reverted to planar.
// Tall tile 32x54 (INH=64): phase-3 amortizes the 10-row tap overhang over
// 7 outputs/thread (12.6 words/output vs 23.6) -> ~1.49x less smem traffic.
// 3 CTAs/SM (63.5KB smem), relaxed reg cap (85).

#define IMG      512
#define TW       32
#define TH       54
#define HALO     5
#define INW      42          // TW + 2*HALO
#define INWP     44          // padded row stride (44*4B, float4-aligned)
#define INH      64          // TH + 2*HALO  (=> phase2 tasks = 64*8 = 512 = 2/thread)
#define NT       256
#define HPLANE   (INH * TW)  // 2048 floats per blurred field

#define GX       16          // 512/32
#define GY       10          // 10*54 = 540 rows, tail masked
#define PL       96
#define NB       (GX * GY * PL)   // 15360 = 15*1024

#define SMEM_FLOATS (2 * INH * INWP + 5 * HPLANE)   // 5632 + 10240 = 15872
#define SMEM_BYTES  (SMEM_FLOATS * 4)               // 63488

__device__ float g_part[NB];
__device__ float g_part2[15];

// 1D gaussian, sigma=1.5, K=11, normalized. Constant indices fold to
// FFMA immediates (rt_SMSP=1 imm-form).
__device__ __forceinline__ constexpr float gw(int k) {
    switch (k) {
        case 0:  return 0.00102838f;
        case 1:  return 0.00759877f;
        case 2:  return 0.03600077f;
        case 3:  return 0.10936069f;
        case 4:  return 0.21300554f;
        case 5:  return 0.26601173f;
        case 6:  return 0.21300554f;
        case 7:  return 0.10936069f;
        case 8:  return 0.03600077f;
        case 9:  return 0.00759877f;
        case 10: return 0.00102838f;
    }
    return 0.0f;
}

__global__ __launch_bounds__(NT, 3)
void ssim_main(const float* __restrict__ img1, const float* __restrict__ img2) {
    extern __shared__ float smem[];
    float* s1 = smem;                       // raw x1 tile [INH][INWP]
    float* s2 = smem + INH * INWP;          // raw x2 tile
    float* sh = smem + 2 * INH * INWP;      // 5 planar fields [INH][TW]
    __shared__ float wsum[NT / 32];

    const int tid = threadIdx.x;
    const int gx0 = blockIdx.x * TW - HALO;
    const int gy0 = blockIdx.y * TH - HALO;
    const size_t pbase = (size_t)blockIdx.z * (IMG * IMG);
    const float* p1 = img1 + pbase;
    const float* p2 = img2 + pbase;

    // ---- Phase 1: global -> smem, (v+1)*0.5, zero-pad OOB. Coalesced:
    //      lanes = 32 contiguous cols; 8 rows per pass, 8 passes. ----
    {
        const int c  = tid & 31;
        const int r8 = tid >> 5;
        #pragma unroll
        for (int rr = r8; rr < INH; rr += 8) {
            const int gy = gy0 + rr;
            const bool rowok = (gy >= 0) && (gy < IMG);
            const float* q1 = p1 + (size_t)gy * IMG;
            const float* q2 = p2 + (size_t)gy * IMG;
            {
                int gx = gx0 + c;
                float v1 = 0.f, v2 = 0.f;
                if (rowok && gx >= 0 && gx < IMG) {
                    v1 = fmaf(q1[gx], 0.5f, 0.5f);
                    v2 = fmaf(q2[gx], 0.5f, 0.5f);
                }
                s1[rr * INWP + c] = v1;
                s2[rr * INWP + c] = v2;
            }
            if (c < 12) {                      // cols 32..43 (42,43 = zero pad)
                int cc = c + 32;
                int gx = gx0 + cc;
                float v1 = 0.f, v2 = 0.f;
                if (c < 10 && rowok && gx >= 0 && gx < IMG) {
                    v1 = fmaf(q1[gx], 0.5f, 0.5f);
                    v2 = fmaf(q2[gx], 0.5f, 0.5f);
                }
                s1[rr * INWP + cc] = v1;
                s2[rr * INWP + cc] = v2;
            }
        }
    }
    __syncthreads();

    // ---- Phase 2: horizontal 11-tap blur, 2 balanced tasks per thread ----
    #pragma unroll
    for (int p = 0; p < 2; p++) {
        const int t   = tid + p * NT;
        const int row = t >> 3;
        const int c0  = (t & 7) << 2;

        float a[16], b[16];
        {
            const float4* a4 = (const float4*)(s1 + row * INWP + c0);
            const float4* b4 = (const float4*)(s2 + row * INWP + c0);
            ((float4*)a)[0] = a4[0]; ((float4*)a)[1] = a4[1];
            ((float4*)a)[2] = a4[2]; ((float4*)a)[3] = a4[3];
            ((float4*)b)[0] = b4[0]; ((float4*)b)[1] = b4[1];
            ((float4*)b)[2] = b4[2]; ((float4*)b)[3] = b4[3];
        }

        float m1[4]  = {0.f, 0.f, 0.f, 0.f};
        float m2[4]  = {0.f, 0.f, 0.f, 0.f};
        float q11[4] = {0.f, 0.f, 0.f, 0.f};
        float q22[4] = {0.f, 0.f, 0.f, 0.f};
        float q12[4] = {0.f, 0.f, 0.f, 0.f};

        #pragma unroll
        for (int i = 0; i < 14; i++) {
            float fa = a[i], fb = b[i];
            float faa = fa * fa, fbb = fb * fb, fab = fa * fb;
            #pragma unroll
            for (int j = 0; j < 4; j++) {
                int k = i - j;
                if (k >= 0 && k < 11) {
                    float w = gw(k);
                    m1[j]  = fmaf(fa,  w, m1[j]);
                    m2[j]  = fmaf(fb,  w, m2[j]);
                    q11[j] = fmaf(faa, w, q11[j]);
                    q22[j] = fmaf(fbb, w, q22[j]);
                    q12[j] = fmaf(fab, w, q12[j]);
                }
            }
        }

        float* hb = sh + row * TW + c0;
        *(float4*)(hb + 0 * HPLANE) = make_float4(m1[0],  m1[1],  m1[2],  m1[3]);
        *(float4*)(hb + 1 * HPLANE) = make_float4(m2[0],  m2[1],  m2[2],  m2[3]);
        *(float4*)(hb + 2 * HPLANE) = make_float4(q11[0], q11[1], q11[2], q11[3]);
        *(float4*)(hb + 3 * HPLANE) = make_float4(q22[0], q22[1], q22[2], q22[3]);
        *(float4*)(hb + 4 * HPLANE) = make_float4(q12[0], q12[1], q12[2], q12[3]);
    }
    __syncthreads();

    // ---- Phase 3: vertical blur + ssim, 7 output rows / thread ----
    const int col = tid & 31;
    const int g   = tid >> 5;
    const int r_start = g * 7;          // 0,7,...,49 (rows 54+ masked)

    float acc0[7], acc1[7], acc2[7], acc3[7], acc4[7];
    #pragma unroll
    for (int j = 0; j < 7; j++) {
        acc0[j] = 0.f; acc1[j] = 0.f; acc2[j] = 0.f; acc3[j] = 0.f; acc4[j] = 0.f;
    }

    #pragma unroll
    for (int i = 0; i < 17; i++) {
        int ri = r_start + i;
        if (ri > INH - 1) ri = INH - 1;   // only contributions to masked rows
        const float* hp = sh + ri * TW + col;
        float h0 = hp[0 * HPLANE];
        float h1 = hp[1 * HPLANE];
        float h2 = hp[2 * HPLANE];
        float h3 = hp[3 * HPLANE];
        float h4 = hp[4 * HPLANE];
        #pragma unroll
        for (int j = 0; j < 7; j++) {
            int k = i - j;
            if (k >= 0 && k < 11) {
                float w = gw(k);
                acc0[j] = fmaf(h0, w, acc0[j]);
                acc1[j] = fmaf(h1, w, acc1[j]);
                acc2[j] = fmaf(h2, w, acc2[j]);
                acc3[j] = fmaf(h3, w, acc3[j]);
                acc4[j] = fmaf(h4, w, acc4[j]);
            }
        }
    }

    const float C1 = 0.0001f;   // 0.01^2
    const float C2 = 0.0009f;   // 0.03^2
    const int   gyb = blockIdx.y * TH + r_start;
    float tsum = 0.f;
    #pragma unroll
    for (int j = 0; j < 7; j++) {
        bool valid = (r_start + j < TH) && (gyb + j < IMG);
        if (valid) {
            float mu1 = acc0[j], mu2 = acc1[j];
            float mu1s = mu1 * mu1, mu2s = mu2 * mu2, mu12 = mu1 * mu2;
            float sA  = acc2[j] - mu1s;
            float sB  = acc3[j] - mu2s;
            float sAB = acc4[j] - mu12;
            float num = (2.f * mu12 + C1) * (2.f * sAB + C2);
            float den = (mu1s + mu2s + C1) * (sA + sB + C2);
            tsum += __fdividef(num, den);
        }
    }

    // ---- Reduction: warp shuffle -> static wsum (1 barrier) -> STG ----
    #pragma unroll
    for (int off = 16; off; off >>= 1)
        tsum += __shfl_xor_sync(0xffffffffu, tsum, off);

    if ((tid & 31) == 0) wsum[tid >> 5] = tsum;
    __syncthreads();
    if (tid == 0) {
        float bs = 0.f;
        #pragma unroll
        for (int i = 0; i < NT / 32; i++) bs += wsum[i];
        int slot = (blockIdx.z * GY + blockIdx.y) * GX + blockIdx.x;
        g_part[slot] = bs;
    }
}

__global__ __launch_bounds__(1024)
void ssim_reduce1() {
    __shared__ float ws[32];
    const int tid = threadIdx.x;
    float s = g_part[blockIdx.x * 1024 + tid];

    #pragma unroll
    for (int off = 16; off; off >>= 1)
        s += __shfl_xor_sync(0xffffffffu, s, off);
    if ((tid & 31) == 0) ws[tid >> 5] = s;
    __syncthreads();
    if (tid < 32) {
        float t = ws[tid];
        #pragma unroll
        for (int off = 16; off; off >>= 1)
            t += __shfl_xor_sync(0xffffffffu, t, off);
        if (tid == 0) g_part2[blockIdx.x] = t;
    }
}

__global__ void ssim_fin(float* out, double inv_n) {
    const int tid = threadIdx.x;   // 32 threads
    double s = (tid < 15) ? (double)g_part2[tid] : 0.0;
    #pragma unroll
    for (int off = 16; off; off >>= 1)
        s += __shfl_xor_sync(0xffffffffu, s, off);
    if (tid == 0) out[0] = 1.0f - (float)(s * inv_n);
}

extern "C" void kernel_launch(void* const* d_in, const int* in_sizes, int n_in,
                              void* d_out, int out_size) {
    const float* img1 = (const float*)d_in[0];
    const float* img2 = (const float*)d_in[1];
    (void)n_in; (void)out_size; (void)in_sizes;

    cudaFuncSetAttribute(ssim_main, cudaFuncAttributeMaxDynamicSharedMemorySize,
                         SMEM_BYTES);

    dim3 grid(GX, GY, PL);
    ssim_main<<<grid, NT, SMEM_BYTES>>>(img1, img2);

    ssim_reduce1<<<15, 1024>>>();
    double inv_n = 1.0 / ((double)PL * IMG * IMG);
    ssim_fin<<<1, 32>>>((float*)d_out, inv_n);
}

// round 10
// speedup vs baseline: 1.6331x; 1.6331x over previous
#include <cuda_runtime.h>

// SSIM loss, fused separable 11x11 gaussian blur + ssim map + mean reduce.
// R10 = R6 (best, 238us) + sum/difference algebra: blur 4 fields
// {s, d, s^2, d^2} with s=x1+x2, d=x1-x2 instead of 5
// {mu1, mu2, x1^2, x2^2, x1x2}. SSIM needs only sigma1^2+sigma2^2 (a sum),
// so 4 fields suffice: mu1mu2=(Bs^2-Bd^2)/4, mu1^2+mu2^2=(Bs^2+Bd^2)/2,
// E12=(Bs2-Bd2)/4, E11+E22=(Bs2+Bd2)/2. Exact algebra, -14% instructions.
// Cross-round invariant: issue% x dur ~ 150us -> instruction count is the
// binding resource at the issue%-maximizing config (6 CTAs/SM, planar).

#define IMG      512
#define TW       32
#define TH       22
#define HALO     5
#define INW      42          // TW + 2*HALO
#define INWP     44          // padded row stride
#define INH      32          // TH + 2*HALO  (=> phase2 tasks = 32*8 = 256)
#define NT       256
#define HPLANE   (INH * TW)  // 1024 floats per blurred field

#define GX       16          // 512/32
#define GY       24          // 24*22 = 528 rows, tail masked
#define PL       96
#define NB       (GX * GY * PL)   // 36864 = 36*1024

#define SMEM_FLOATS (2 * INH * INWP + 4 * HPLANE)   // 2816 + 4096 = 6912
#define SMEM_BYTES  (SMEM_FLOATS * 4)               // 27648

__device__ float g_part[NB];
__device__ float g_part2[36];

// 1D gaussian, sigma=1.5, K=11, normalized. Constant indices fold to
// FFMA immediates (rt_SMSP=1 imm-form).
__device__ __forceinline__ constexpr float gw(int k) {
    switch (k) {
        case 0:  return 0.00102838f;
        case 1:  return 0.00759877f;
        case 2:  return 0.03600077f;
        case 3:  return 0.10936069f;
        case 4:  return 0.21300554f;
        case 5:  return 0.26601173f;
        case 6:  return 0.21300554f;
        case 7:  return 0.10936069f;
        case 8:  return 0.03600077f;
        case 9:  return 0.00759877f;
        case 10: return 0.00102838f;
    }
    return 0.0f;
}

__global__ __launch_bounds__(NT, 6)
void ssim_main(const float* __restrict__ img1, const float* __restrict__ img2) {
    extern __shared__ float smem[];
    float* ss = smem;                       // s = x1+x2 tile [INH][INWP]
    float* sd = smem + INH * INWP;          // d = x1-x2 tile
    float* sh = smem + 2 * INH * INWP;      // 4 planar fields [INH][TW]
    __shared__ float wsum[NT / 32];

    const int tid = threadIdx.x;
    const int gx0 = blockIdx.x * TW - HALO;
    const int gy0 = blockIdx.y * TH - HALO;
    const size_t pbase = (size_t)blockIdx.z * (IMG * IMG);
    const float* p1 = img1 + pbase;
    const float* p2 = img2 + pbase;

    // ---- Phase 1: global -> smem. s=(i1+i2)*0.5+1, d=(i1-i2)*0.5.
    //      Zero-pad OOB (x1=x2=0 => s=0, d=0). ----
    {
        const int r  = tid >> 3;
        const int c  = tid & 7;
        const int gy = gy0 + r;
        const bool rowok = (gy >= 0) && (gy < IMG);
        const float* q1 = p1 + (size_t)gy * IMG;
        const float* q2 = p2 + (size_t)gy * IMG;
        #pragma unroll
        for (int k = 0; k < 6; k++) {
            int cc = c + 8 * k;
            if (k < 5 || cc < INWP) {
                int gx = gx0 + cc;
                float vs = 0.f, vd = 0.f;
                if (rowok && cc < INW && gx >= 0 && gx < IMG) {
                    float a = q1[gx], b = q2[gx];
                    vs = fmaf(a + b, 0.5f, 1.0f);
                    vd = (a - b) * 0.5f;
                }
                ss[r * INWP + cc] = vs;
                sd[r * INWP + cc] = vd;
            }
        }
    }
    __syncthreads();

    // ---- Phase 2: horizontal 11-tap blur of {s, d, s^2, d^2},
    //      exactly one task (4 output cols) per thread ----
    {
        const int row = tid >> 3;
        const int c0  = (tid & 7) << 2;

        float a[16], b[16];
        {
            const float4* a4 = (const float4*)(ss + row * INWP + c0);
            const float4* b4 = (const float4*)(sd + row * INWP + c0);
            ((float4*)a)[0] = a4[0]; ((float4*)a)[1] = a4[1];
            ((float4*)a)[2] = a4[2]; ((float4*)a)[3] = a4[3];
            ((float4*)b)[0] = b4[0]; ((float4*)b)[1] = b4[1];
            ((float4*)b)[2] = b4[2]; ((float4*)b)[3] = b4[3];
        }

        float fs[4]  = {0.f, 0.f, 0.f, 0.f};
        float fd[4]  = {0.f, 0.f, 0.f, 0.f};
        float fs2[4] = {0.f, 0.f, 0.f, 0.f};
        float fd2[4] = {0.f, 0.f, 0.f, 0.f};

        #pragma unroll
        for (int i = 0; i < 14; i++) {
            float vs = a[i], vd = b[i];
            float vss = vs * vs, vdd = vd * vd;
            #pragma unroll
            for (int j = 0; j < 4; j++) {
                int k = i - j;
                if (k >= 0 && k < 11) {
                    float w = gw(k);
                    fs[j]  = fmaf(vs,  w, fs[j]);
                    fd[j]  = fmaf(vd,  w, fd[j]);
                    fs2[j] = fmaf(vss, w, fs2[j]);
                    fd2[j] = fmaf(vdd, w, fd2[j]);
                }
            }
        }

        float* hb = sh + row * TW + c0;
        *(float4*)(hb + 0 * HPLANE) = make_float4(fs[0],  fs[1],  fs[2],  fs[3]);
        *(float4*)(hb + 1 * HPLANE) = make_float4(fd[0],  fd[1],  fd[2],  fd[3]);
        *(float4*)(hb + 2 * HPLANE) = make_float4(fs2[0], fs2[1], fs2[2], fs2[3]);
        *(float4*)(hb + 3 * HPLANE) = make_float4(fd2[0], fd2[1], fd2[2], fd2[3]);
    }
    __syncthreads();

    // ---- Phase 3: vertical blur + ssim. groups 0-5: 3 rows, 6-7: 2 rows ----
    const int col = tid & 31;
    const int g   = tid >> 5;
    const int r_start = (g < 6) ? 3 * g : 18 + 2 * (g - 6);

    float acc0[3], acc1[3], acc2[3], acc3[3];
    #pragma unroll
    for (int j = 0; j < 3; j++) {
        acc0[j] = 0.f; acc1[j] = 0.f; acc2[j] = 0.f; acc3[j] = 0.f;
    }

    #pragma unroll
    for (int i = 0; i < 13; i++) {
        int ri = r_start + i;
        if (ri > INH - 1) ri = INH - 1;   // only dead lanes hit clamp
        const float* hp = sh + ri * TW + col;
        float h0 = hp[0 * HPLANE];
        float h1 = hp[1 * HPLANE];
        float h2 = hp[2 * HPLANE];
        float h3 = hp[3 * HPLANE];
        #pragma unroll
        for (int j = 0; j < 3; j++) {
            int k = i - j;
            if (k >= 0 && k < 11) {
                float w = gw(k);
                acc0[j] = fmaf(h0, w, acc0[j]);
                acc1[j] = fmaf(h1, w, acc1[j]);
                acc2[j] = fmaf(h2, w, acc2[j]);
                acc3[j] = fmaf(h3, w, acc3[j]);
            }
        }
    }

    const float C1 = 0.0001f;   // 0.01^2
    const float C2 = 0.0009f;   // 0.03^2
    const int   gyb = blockIdx.y * TH + r_start;
    float tsum = 0.f;
    #pragma unroll
    for (int j = 0; j < 3; j++) {
        bool valid = (j < 2 || g < 6) && (gyb + j < IMG);
        if (valid) {
            float Bs  = acc0[j], Bd  = acc1[j];
            float Bs2 = acc2[j], Bd2 = acc3[j];
            float bss = Bs * Bs, bdd = Bd * Bd;
            float mu12   = 0.25f * (bss - bdd);        // mu1*mu2
            float musq   = 0.50f * (bss + bdd);        // mu1^2 + mu2^2
            float sig12  = 0.25f * (Bs2 - Bd2) - mu12; // sigma12
            float sigsum = 0.50f * (Bs2 + Bd2) - musq; // sigma1^2 + sigma2^2
            float num = fmaf(2.f, mu12,  C1) * fmaf(2.f, sig12, C2);
            float den = (musq + C1) * (sigsum + C2);
            tsum += __fdividef(num, den);
        }
    }

    // ---- Reduction: warp shuffle -> static wsum (1 barrier) -> STG ----
    #pragma unroll
    for (int off = 16; off; off >>= 1)
        tsum += __shfl_xor_sync(0xffffffffu, tsum, off);

    if ((tid & 31) == 0) wsum[tid >> 5] = tsum;
    __syncthreads();
    if (tid == 0) {
        float bs = 0.f;
        #pragma unroll
        for (int i = 0; i < NT / 32; i++) bs += wsum[i];
        int slot = (blockIdx.z * GY + blockIdx.y) * GX + blockIdx.x;
        g_part[slot] = bs;
    }
}

__global__ __launch_bounds__(1024)
void ssim_reduce1() {
    __shared__ float ws[32];
    const int tid = threadIdx.x;
    float s = g_part[blockIdx.x * 1024 + tid];

    #pragma unroll
    for (int off = 16; off; off >>= 1)
        s += __shfl_xor_sync(0xffffffffu, s, off);
    if ((tid & 31) == 0) ws[tid >> 5] = s;
    __syncthreads();
    if (tid < 32) {
        float t = ws[tid];
        #pragma unroll
        for (int off = 16; off; off >>= 1)
            t += __shfl_xor_sync(0xffffffffu, t, off);
        if (tid == 0) g_part2[blockIdx.x] = t;
    }
}

__global__ void ssim_fin(float* out, double inv_n) {
    const int tid = threadIdx.x;   // 32 threads
    double s = (double)g_part2[tid];
    if (tid < 4) s += (double)g_part2[tid + 32];
    #pragma unroll
    for (int off = 16; off; off >>= 1)
        s += __shfl_xor_sync(0xffffffffu, s, off);
    if (tid == 0) out[0] = 1.0f - (float)(s * inv_n);
}

extern "C" void kernel_launch(void* const* d_in, const int* in_sizes, int n_in,
                              void* d_out, int out_size) {
    const float* img1 = (const float*)d_in[0];
    const float* img2 = (const float*)d_in[1];
    (void)n_in; (void)out_size; (void)in_sizes;

    cudaFuncSetAttribute(ssim_main, cudaFuncAttributeMaxDynamicSharedMemorySize,
                         SMEM_BYTES);

    dim3 grid(GX, GY, PL);
    ssim_main<<<grid, NT, SMEM_BYTES>>>(img1, img2);

    ssim_reduce1<<<36, 1024>>>();
    double inv_n = 1.0 / ((double)PL * IMG * IMG);
    ssim_fin<<<1, 32>>>((float*)d_out, inv_n);
}